// round 7
// baseline (speedup 1.0000x reference)
#include <cuda_runtime.h>
#include <cstdint>

// s1, blur: [4, 10, 256, 256] fp32 -> out: [4, 256, 256] fp32.
//
// Per pixel: candidate i (0..10): x_j = s_j + b_j (j<i) else s_j - b_j.
// argmin_i std(x); output mean of winner.
// Identity: argmin variance == argmin( 4*P_i - sum_i^2/n ),
//   P_i = prefix sum of s_j*b_j, sum_i = (S-B) + 2*prefix sum of b_j.
//
// Persistent pipelined streaming: every prior variant (LDG scalar/64/128,
// TMA one-shot; occ 19%..67%) saturated at ~2.5-2.8 TB/s because loads are
// only in flight during each CTA's front-batch phase. Here 304 persistent
// CTAs each run a 4-stage cp.async ring (10KB/stage): 20-30KB of copies
// in flight per CTA at ALL times, compute overlapped with copies.

#define NPLANES  10
#define HW       65536        // 256*256
#define THREADS  128
#define CHUNK    128          // pixels per stage (divides HW)
#define STAGES   4
#define NCHUNKS  2048         // 262144 / CHUNK
#define BLOCKS   304          // ~2 per SM on 148-152 SMs

__device__ __forceinline__ uint32_t smem_u32(const void* p) {
    return (uint32_t)__cvta_generic_to_shared(p);
}

__device__ __forceinline__ void cp16(uint32_t dst, const void* src) {
    asm volatile("cp.async.cg.shared.global [%0], [%1], 16;"
                 :: "r"(dst), "l"(src));
}

__global__ __launch_bounds__(THREADS)
void distreg_kernel(const float* __restrict__ s1,
                    const float* __restrict__ blur,
                    float* __restrict__ out)
{
    // [stage][row][pix] ; rows 0..9 = s1 planes, 10..19 = blur planes
    __shared__ float sm[STAGES][2 * NPLANES][CHUNK];

    const int tid = threadIdx.x;
    const int bid = blockIdx.x;

    // number of chunks this block processes (grid-stride over chunks)
    const int myn = (NCHUNKS - bid + BLOCKS - 1) / BLOCKS;   // 6 or 7

    // Each thread issues 5 x 16B cp.async per stage (640 x 16B = 10KB).
    // flat f = tid + i*128 ; row = f>>5 (0..19) ; q = f&31 (16B unit in row).
    auto issue_stage = [&](int chunk, int st) {
        int b   = chunk >> 9;                 // chunk*128 / HW
        int hw0 = (chunk << 7) & (HW - 1);
        const float* sp = s1   + ((size_t)b * NPLANES) * HW + hw0;
        const float* bp = blur + ((size_t)b * NPLANES) * HW + hw0;
        #pragma unroll
        for (int i = 0; i < 5; i++) {
            int f   = tid + i * THREADS;
            int row = f >> 5;
            int q   = f & 31;
            const float* g = (row < NPLANES)
                ? (sp + (size_t)row * HW + q * 4)
                : (bp + (size_t)(row - NPLANES) * HW + q * 4);
            cp16(smem_u32(&sm[st][row][q * 4]), g);
        }
    };

    // Prologue: fill STAGES-1 = 3 stages (always valid: myn >= 6).
    #pragma unroll
    for (int k = 0; k < STAGES - 1; k++) {
        issue_stage(bid + k * BLOCKS, k);
        asm volatile("cp.async.commit_group;" ::: "memory");
    }

    const float inv_n = 1.0f / NPLANES;

    for (int k = 0; k < myn; k++) {
        // groups complete in order: wait until group k done (<=2 pending).
        asm volatile("cp.async.wait_group 2;" ::: "memory");
        __syncthreads();

        const int st    = k & (STAGES - 1);
        const int chunk = bid + k * BLOCKS;

        // Compute pixel `tid` of this chunk from smem (stride-1, no conflicts).
        float sv[NPLANES], bv[NPLANES];
        float S = 0.f, B = 0.f;
        #pragma unroll
        for (int j = 0; j < NPLANES; j++) {
            sv[j] = sm[st][j][tid];
            bv[j] = sm[st][NPLANES + j][tid];
            S += sv[j];
            B += bv[j];
        }

        float sum = S - B;      // candidate 0: all lo
        float P   = 0.f;        // prefix sum of s_j*b_j
        float bestM = 3.0e38f, bestSum = sum;
        #pragma unroll
        for (int i = 0; i <= NPLANES; i++) {
            float M = fmaf(-sum * inv_n, sum, 4.0f * P);
            if (M < bestM) { bestM = M; bestSum = sum; }   // first index wins ties
            if (i < NPLANES) {
                sum = fmaf(2.0f, bv[i], sum);
                P   = fmaf(sv[i], bv[i], P);
            }
        }
        out[(chunk << 7) + tid] = bestSum * inv_n;

        __syncthreads();   // all threads done reading stage before refill

        if (k + STAGES - 1 < myn)
            issue_stage(bid + (k + STAGES - 1) * BLOCKS, (k + STAGES - 1) & (STAGES - 1));
        // Always commit (possibly-empty group) to keep wait_group accounting.
        asm volatile("cp.async.commit_group;" ::: "memory");
    }
}

extern "C" void kernel_launch(void* const* d_in, const int* in_sizes, int n_in,
                              void* d_out, int out_size)
{
    const float* s1   = (const float*)d_in[0];
    const float* blur = (const float*)d_in[1];
    float* out = (float*)d_out;

    distreg_kernel<<<BLOCKS, THREADS>>>(s1, blur, out);
}

// round 8
// speedup vs baseline: 1.3430x; 1.3430x over previous
#include <cuda_runtime.h>
#include <cstdint>

// s1, blur: [4, 10, 256, 256] fp32 -> out: [4, 256, 256] fp32.
//
// Per pixel: candidate i (0..10): x_j = s_j + b_j (j<i) else s_j - b_j.
// argmin_i std(x); output mean of winner.
// Identity: argmin variance == argmin( 4*P_i - sum_i^2/n ),
//   P_i = prefix sum s_j*b_j ; sum_i = (S-B) + 2*prefix sum b_j.
//
// Six load-path designs all hit ~2.5-2.8 TB/s cold. This round's lever:
// ld.global.nc.L2::256B -- 256B DRAM fetch granule per request (dense
// access, zero overfetch) to improve HBM burst efficiency.

#define NPLANES 10
#define HW      65536    // 256*256
#define HW2     32768

__device__ __forceinline__ float2 ldg_nc_256(const float2* p) {
    float2 r;
    asm volatile("ld.global.nc.L2::256B.v2.f32 {%0, %1}, [%2];"
                 : "=f"(r.x), "=f"(r.y) : "l"(p));
    return r;
}

__global__ __launch_bounds__(128, 8)
void distregression_kernel(const float2* __restrict__ s1,
                           const float2* __restrict__ blur,
                           float2* __restrict__ out,
                           int npairs)
{
    int t = blockIdx.x * blockDim.x + threadIdx.x;
    if (t >= npairs) return;

    int b   = t >> 15;            // pair / HW2 -> batch
    int hw2 = t & (HW2 - 1);

    const float2* s1p = s1   + (size_t)b * NPLANES * HW2 + hw2;
    const float2* blp = blur + (size_t)b * NPLANES * HW2 + hw2;

    // Front-batch all 20 vector loads (MLP=20, 256B L2 fetch granule).
    float sv[NPLANES][2], bv[NPLANES][2];
    #pragma unroll
    for (int j = 0; j < NPLANES; j++) {
        float2 s = ldg_nc_256(s1p + j * HW2);
        float2 v = ldg_nc_256(blp + j * HW2);
        sv[j][0] = s.x; sv[j][1] = s.y;
        bv[j][0] = v.x; bv[j][1] = v.y;
    }

    const float inv_n = 1.0f / NPLANES;
    float res[2];
    #pragma unroll
    for (int k = 0; k < 2; k++) {
        float S = 0.f, B = 0.f;
        #pragma unroll
        for (int j = 0; j < NPLANES; j++) {
            S += sv[j][k];
            B += bv[j][k];
        }

        float sum = S - B;      // candidate 0: all lo
        float P   = 0.f;        // prefix sum of s_j*b_j
        float bestM = 3.0e38f, bestSum = sum;

        #pragma unroll
        for (int i = 0; i <= NPLANES; i++) {
            float M = fmaf(-sum * inv_n, sum, 4.0f * P);
            if (M < bestM) { bestM = M; bestSum = sum; }   // first index wins ties
            if (i < NPLANES) {
                sum = fmaf(2.0f, bv[i][k], sum);
                P   = fmaf(sv[i][k], bv[i][k], P);
            }
        }
        res[k] = bestSum * inv_n;
    }

    out[t] = make_float2(res[0], res[1]);
}

extern "C" void kernel_launch(void* const* d_in, const int* in_sizes, int n_in,
                              void* d_out, int out_size)
{
    const float2* s1   = (const float2*)d_in[0];
    const float2* blur = (const float2*)d_in[1];
    float2* out = (float2*)d_out;

    int npairs  = out_size / 2;                    // 131072
    int threads = 128;
    int blocks  = (npairs + threads - 1) / threads;  // 1024
    distregression_kernel<<<blocks, threads>>>(s1, blur, out, npairs);
}